// round 5
// baseline (speedup 1.0000x reference)
#include <cuda_runtime.h>
#include <cuda_bf16.h>
#include <cuda_fp16.h>
#include <mma.h>
#include <cstdint>

using namespace nvcuda;

#define BATCH 16
#define L 1024
#define D 768
#define G2 768            // group rows per batch (max g = 511+255 = 766)
#define BIG 1e30f

// -------- device scratch (allocation-free rule: __device__ globals) --------
__device__ __nv_bfloat16 g_s1n[BATCH * L * D];                 // 25 MB
__device__ __nv_bfloat16 g_s2n[BATCH * L * D];                 // 25 MB
// dist (=1-dot) as half, DTW-step layout: cell (i,j) ->
// g_dskH[b][g][jg][r][c], g = i/2 + j/4, jg = j/4, r = i&1, c = j&3.
__device__ __half g_dskH[(size_t)BATCH * G2 * 2048];           // 48 MB

// ---------------------------------------------------------------------------
// helpers
// ---------------------------------------------------------------------------
__device__ __forceinline__ uint32_t smem_u32(const void* p) {
    uint32_t a;
    asm("{ .reg .u64 t; cvta.to.shared.u64 t, %1; cvt.u32.u64 %0, t; }"
        : "=r"(a) : "l"(p));
    return a;
}
__device__ __forceinline__ void cp16(uint32_t dst, const void* src) {
    asm volatile("cp.async.cg.shared.global [%0], [%1], 16;"
                 :: "r"(dst), "l"(src) : "memory");
}
#define CP_COMMIT() asm volatile("cp.async.commit_group;" ::: "memory")
#define CP_WAIT2()  asm volatile("cp.async.wait_group 2;" ::: "memory")
#define CP_WAIT0()  asm volatile("cp.async.wait_group 0;" ::: "memory")

__device__ __forceinline__ void st_release_cta(uint32_t addr, int v) {
    asm volatile("st.release.cta.shared.b32 [%0], %1;" :: "r"(addr), "r"(v) : "memory");
}
__device__ __forceinline__ int ld_acquire_cta(uint32_t addr) {
    int v;
    asm volatile("ld.acquire.cta.shared.b32 %0, [%1];" : "=r"(v) : "r"(addr) : "memory");
    return v;
}

// ---------------------------------------------------------------------------
// Kernel 1: L2-normalize. One warp per row, float4 loads, shfl reduction.
// ---------------------------------------------------------------------------
__global__ __launch_bounds__(256) void normalize_kernel(const float* __restrict__ s1,
                                                        const float* __restrict__ s2) {
    int wid = threadIdx.x >> 5, lane = threadIdx.x & 31;
    int row = blockIdx.x * 8 + wid;          // 0 .. 32767
    const float* src;
    __nv_bfloat16* dst;
    if (row < BATCH * L) {
        src = s1 + (size_t)row * D;
        dst = g_s1n + (size_t)row * D;
    } else {
        int r = row - BATCH * L;
        src = s2 + (size_t)r * D;
        dst = g_s2n + (size_t)r * D;
    }
    const float4* s4 = (const float4*)src;
    float4 v[6];
    float ss = 0.f;
    #pragma unroll
    for (int i = 0; i < 6; i++) {
        v[i] = s4[lane + 32 * i];
        ss += v[i].x * v[i].x + v[i].y * v[i].y + v[i].z * v[i].z + v[i].w * v[i].w;
    }
    #pragma unroll
    for (int o = 16; o > 0; o >>= 1) ss += __shfl_xor_sync(0xffffffffu, ss, o);
    float inv = rsqrtf(ss);
    #pragma unroll
    for (int i = 0; i < 6; i++) {
        __nv_bfloat162 a = __floats2bfloat162_rn(v[i].x * inv, v[i].y * inv);
        __nv_bfloat162 b = __floats2bfloat162_rn(v[i].z * inv, v[i].w * inv);
        uint2 pk;
        pk.x = *(const uint32_t*)&a;
        pk.y = *(const uint32_t*)&b;
        ((uint2*)dst)[lane + 32 * i] = pk;
    }
}

// ---------------------------------------------------------------------------
// Kernel 2: wmma bf16 GEMM. CTA 128x128, BK=32, 8 warps (2Mx4N, 64x32 warp
// tile), 4-stage/3-deep cp.async pipeline, LDA_S=40 (conflict-free 80B rows),
// __launch_bounds__(256,2) for 2 CTAs/SM. Epilogue: acc -> smem -> packed
// half uint4 stores of dist = 1 - dot into g_dskH.
// ---------------------------------------------------------------------------
#define BM 128
#define BN 128
#define BK 32
#define STAGES 4
#define NITER (D / BK)    // 24
#define LDA_S 40          // padded bf16 smem row (80 B)
#define LDC_S 132         // padded fp32 epi row
#define STAGE_ELEMS (BM * LDA_S)              // per matrix per stage (bf16)
#define STAGE_BYTES (2 * STAGE_ELEMS * 2)     // A+B per stage = 20480 B
#define SMEM_BYTES (STAGES * STAGE_BYTES)     // 81920 B (>= 128*132*4 epi)

__global__ __launch_bounds__(256, 2) void gemm_dist_kernel() {
    extern __shared__ char smem[];
    __nv_bfloat16* sA[STAGES];
    __nv_bfloat16* sB[STAGES];
    #pragma unroll
    for (int s = 0; s < STAGES; s++) {
        sA[s] = (__nv_bfloat16*)(smem + s * STAGE_BYTES);
        sB[s] = sA[s] + STAGE_ELEMS;
    }

    int tid = threadIdx.x;
    int b  = blockIdx.z;
    int m0 = blockIdx.y * BM;
    int n0 = blockIdx.x * BN;
    const __nv_bfloat16* A  = g_s1n + (size_t)b * L * D;
    const __nv_bfloat16* Bm = g_s2n + (size_t)b * L * D;

    int warp = tid >> 5;
    int wm = warp & 1;        // 2 warps in M (64 rows)
    int wn = warp >> 1;       // 4 warps in N (32 cols)

    // load indices: chunk id = tid + it*256, row = id>>2, col = (id&3)*8
    int lr = tid >> 2;        // 0..63
    int lc = (tid & 3) * 8;

    wmma::fragment<wmma::accumulator, 16, 16, 16, float> acc[4][2];
    #pragma unroll
    for (int mi = 0; mi < 4; mi++)
        #pragma unroll
        for (int ni = 0; ni < 2; ni++)
            wmma::fill_fragment(acc[mi][ni], 0.0f);

    // prologue: stages 0..2 (3 groups in flight)
    #pragma unroll
    for (int s = 0; s < 3; s++) {
        int k0 = s * BK;
        #pragma unroll
        for (int it = 0; it < 2; it++) {
            cp16(smem_u32(&sA[s][(lr + it * 64) * LDA_S + lc]),
                 A + (size_t)(m0 + lr + it * 64) * D + k0 + lc);
            cp16(smem_u32(&sB[s][(lr + it * 64) * LDA_S + lc]),
                 Bm + (size_t)(n0 + lr + it * 64) * D + k0 + lc);
        }
        CP_COMMIT();
    }

    for (int c = 0; c < NITER; c++) {
        CP_WAIT2();
        __syncthreads();
        int st = c & 3;

        #pragma unroll
        for (int kk = 0; kk < BK; kk += 16) {
            wmma::fragment<wmma::matrix_a, 16, 16, 16, __nv_bfloat16, wmma::row_major> af[4];
            wmma::fragment<wmma::matrix_b, 16, 16, 16, __nv_bfloat16, wmma::col_major> bf[2];
            #pragma unroll
            for (int mi = 0; mi < 4; mi++)
                wmma::load_matrix_sync(af[mi], &sA[st][(wm * 64 + mi * 16) * LDA_S + kk], LDA_S);
            #pragma unroll
            for (int ni = 0; ni < 2; ni++)
                wmma::load_matrix_sync(bf[ni], &sB[st][(wn * 32 + ni * 16) * LDA_S + kk], LDA_S);
            #pragma unroll
            for (int mi = 0; mi < 4; mi++)
                #pragma unroll
                for (int ni = 0; ni < 2; ni++)
                    wmma::mma_sync(acc[mi][ni], af[mi], bf[ni], acc[mi][ni]);
        }

        if (c + 3 < NITER) {
            int sn = (c + 3) & 3;
            int k0 = (c + 3) * BK;
            #pragma unroll
            for (int it = 0; it < 2; it++) {
                cp16(smem_u32(&sA[sn][(lr + it * 64) * LDA_S + lc]),
                     A + (size_t)(m0 + lr + it * 64) * D + k0 + lc);
                cp16(smem_u32(&sB[sn][(lr + it * 64) * LDA_S + lc]),
                     Bm + (size_t)(n0 + lr + it * 64) * D + k0 + lc);
            }
        }
        CP_COMMIT();
    }

    // epilogue: acc -> smem (reuse stages), packed half uint4 stores
    CP_WAIT0();
    __syncthreads();
    float* Cs = (float*)smem;
    #pragma unroll
    for (int mi = 0; mi < 4; mi++)
        #pragma unroll
        for (int ni = 0; ni < 2; ni++)
            wmma::store_matrix_sync(&Cs[(wm * 64 + mi * 16) * LDC_S + (wn * 32 + ni * 16)],
                                    acc[mi][ni], LDC_S, wmma::mem_row_major);
    __syncthreads();

    __half* dbase = g_dskH + (size_t)b * G2 * 2048;
    int jgl = tid & 31;           // local j group (4 cols), col = n0 + 4*jgl
    int sub = tid >> 5;           // 0..7

    #pragma unroll
    for (int it = 0; it < 8; it++) {
        int il2 = sub + it * 8;                      // local row pair 0..63
        float4 r0 = *(float4*)&Cs[(2 * il2)     * LDC_S + 4 * jgl];
        float4 r1 = *(float4*)&Cs[(2 * il2 + 1) * LDC_S + 4 * jgl];
        uint4 o;
        __half2* ph = (__half2*)&o;
        ph[0] = __floats2half2_rn(1.0f - r0.x, 1.0f - r0.y);
        ph[1] = __floats2half2_rn(1.0f - r0.z, 1.0f - r0.w);
        ph[2] = __floats2half2_rn(1.0f - r1.x, 1.0f - r1.y);
        ph[3] = __floats2half2_rn(1.0f - r1.z, 1.0f - r1.w);
        int g = (m0 >> 1) + il2 + (n0 >> 2) + jgl;
        *(uint4*)(dbase + (size_t)g * 2048 + ((n0 >> 2) + jgl) * 8) = o;
    }
}

// ---------------------------------------------------------------------------
// Kernel 3: DTW wavefront, barrier-free. 256 threads, thread jg owns cols
// [4jg,4jg+4), 2 rows per step, 768 steps. Warps pipeline via a full
// per-step boundary journal in smem + release/acquire progress counters;
// no __syncthreads inside the loop. Only lane 0 of each warp spins.
// ---------------------------------------------------------------------------
#define PF 8

__global__ __launch_bounds__(256) void dtw_kernel(float* __restrict__ out) {
    extern __shared__ float pubd[];                 // [8][768][2] = 49152 B
    __shared__ int prog[8];

    int b = blockIdx.x;
    int jg = threadIdx.x, lane = jg & 31, w = jg >> 5;

    if (jg < 8) prog[jg] = -1;
    __syncthreads();

    uint32_t my_prog   = smem_u32(&prog[w]);
    uint32_t prev_prog = smem_u32(&prog[w > 0 ? w - 1 : 0]);
    float* mypub   = pubd + (size_t)w * 768 * 2;
    const float* prevpub = pubd + (size_t)(w > 0 ? w - 1 : 0) * 768 * 2;

    const uint4* base = (const uint4*)(g_dskH + (size_t)b * G2 * 2048) + jg;
    // g row stride = 2048 halfs = 256 uint4

    float p0 = BIG, p1 = BIG, p2 = BIG, p3 = BIG;   // prev row of own 4 cols
    float c3r0 = BIG, c3r1 = BIG, prev_vb = BIG;
    float res = 0.0f;

    uint4 ring[PF];
    #pragma unroll
    for (int s = 0; s < PF; s++)
        ring[s] = base[(size_t)min(s, G2 - 1) * 256];

    #pragma unroll 4
    for (int S = 0; S < 768; S++) {
        uint4 u = ring[S & (PF - 1)];
        ring[S & (PF - 1)] = base[(size_t)min(S + PF, G2 - 1) * 256];

        float va = __shfl_up_sync(0xffffffffu, c3r0, 1);  // dtw[i0][4jg-1]
        float vb = __shfl_up_sync(0xffffffffu, c3r1, 1);  // dtw[i0+1][4jg-1]
        if (lane == 0) {
            va = BIG; vb = BIG;
            if (w > 0 && S > 0) {
                while (ld_acquire_cta(prev_prog) < S - 1) { }
                va = prevpub[(S - 1) * 2 + 0];
                vb = prevpub[(S - 1) * 2 + 1];
            }
        }

        int i0 = 2 * (S - jg);
        if ((unsigned)i0 < 1024u) {
            float2 q0 = __half22float2(((const __half2*)&u)[0]);
            float2 q1 = __half22float2(((const __half2*)&u)[1]);
            float2 q2 = __half22float2(((const __half2*)&u)[2]);
            float2 q3 = __half22float2(((const __half2*)&u)[3]);
            // row i0 (min-plus prefix form)
            float D0 = q0.x, D1 = D0 + q0.y, D2 = D1 + q1.x, D3 = D2 + q1.y;
            float f0 = fminf(prev_vb, p0);
            float f1 = fminf(p0, p1) - D0;
            float f2 = fminf(p1, p2) - D1;
            float f3 = fminf(p2, p3) - D2;
            float m0 = fminf(va, f0);
            if (i0 == 0 && jg == 0) m0 = 0.0f;
            float m1 = fminf(m0, f1);
            float m2 = fminf(m1, f2);
            float m3 = fminf(m2, f3);
            float c0 = D0 + m0, c1 = D1 + m1, c2 = D2 + m2, c3 = D3 + m3;
            // row i0+1
            float E0 = q2.x, E1 = E0 + q2.y, E2 = E1 + q3.x, E3 = E2 + q3.y;
            float h0 = fminf(va, c0);
            float h1 = fminf(c0, c1) - E0;
            float h2 = fminf(c1, c2) - E1;
            float h3 = fminf(c2, c3) - E2;
            float n0 = fminf(vb, h0);
            float n1 = fminf(n0, h1);
            float n2 = fminf(n1, h2);
            float n3 = fminf(n2, h3);
            p0 = E0 + n0; p1 = E1 + n1; p2 = E2 + n2; p3 = E3 + n3;
            c3r0 = c3; c3r1 = p3;
            if (i0 == 1022 && jg == 255) res = p3;
        }
        prev_vb = vb;
        if (lane == 31 && w < 7) {
            mypub[S * 2 + 0] = c3r0;
            mypub[S * 2 + 1] = c3r1;
            st_release_cta(my_prog, S);
        }
    }

    if (jg == 255)
        out[b] = 1.0f / (1.0f + res * (1.0f / 2048.0f));
}

// ---------------------------------------------------------------------------
extern "C" void kernel_launch(void* const* d_in, const int* in_sizes, int n_in,
                              void* d_out, int out_size) {
    const float* s1 = (const float*)d_in[0];
    const float* s2 = (const float*)d_in[1];
    float* out = (float*)d_out;

    cudaFuncSetAttribute(gemm_dist_kernel,
                         cudaFuncAttributeMaxDynamicSharedMemorySize, SMEM_BYTES);
    cudaFuncSetAttribute(dtw_kernel,
                         cudaFuncAttributeMaxDynamicSharedMemorySize, 8 * 768 * 2 * 4);

    normalize_kernel<<<4096, 256>>>(s1, s2);
    gemm_dist_kernel<<<dim3(L / BN, L / BM, BATCH), 256, SMEM_BYTES>>>();
    dtw_kernel<<<BATCH, 256, 8 * 768 * 2 * 4>>>(out);
}

// round 6
// speedup vs baseline: 1.0059x; 1.0059x over previous
#include <cuda_runtime.h>
#include <cuda_bf16.h>
#include <cuda_fp16.h>
#include <mma.h>
#include <cstdint>

using namespace nvcuda;

#define BATCH 16
#define L 1024
#define D 768
#define G2 768            // group rows per batch (max g = 511+255 = 766)
#define BIG 1e30f

// -------- device scratch (allocation-free rule: __device__ globals) --------
__device__ __nv_bfloat16 g_s1n[BATCH * L * D];                 // 25 MB
__device__ __nv_bfloat16 g_s2n[BATCH * L * D];                 // 25 MB
// dist (=1-dot) as half, DTW-step layout: cell (i,j) ->
// g_dskH[b][g][jg][r][c], g = i/2 + j/4, jg = j/4, r = i&1, c = j&3.
__device__ __half g_dskH[(size_t)BATCH * G2 * 2048];           // 48 MB

// ---------------------------------------------------------------------------
// helpers
// ---------------------------------------------------------------------------
__device__ __forceinline__ uint32_t smem_u32(const void* p) {
    uint32_t a;
    asm("{ .reg .u64 t; cvta.to.shared.u64 t, %1; cvt.u32.u64 %0, t; }"
        : "=r"(a) : "l"(p));
    return a;
}
__device__ __forceinline__ void cp16(uint32_t dst, const void* src) {
    asm volatile("cp.async.cg.shared.global [%0], [%1], 16;"
                 :: "r"(dst), "l"(src) : "memory");
}
#define CP_COMMIT() asm volatile("cp.async.commit_group;" ::: "memory")
#define CP_WAIT1()  asm volatile("cp.async.wait_group 1;" ::: "memory")
#define CP_WAIT0()  asm volatile("cp.async.wait_group 0;" ::: "memory")

__device__ __forceinline__ void st_release_cta(uint32_t addr, int v) {
    asm volatile("st.release.cta.shared.b32 [%0], %1;" :: "r"(addr), "r"(v) : "memory");
}
__device__ __forceinline__ int ld_acquire_cta(uint32_t addr) {
    int v;
    asm volatile("ld.acquire.cta.shared.b32 %0, [%1];" : "=r"(v) : "r"(addr) : "memory");
    return v;
}

// ---------------------------------------------------------------------------
// Kernel 1: L2-normalize. One warp per row, float4 loads, shfl reduction.
// ---------------------------------------------------------------------------
__global__ __launch_bounds__(256) void normalize_kernel(const float* __restrict__ s1,
                                                        const float* __restrict__ s2) {
    int wid = threadIdx.x >> 5, lane = threadIdx.x & 31;
    int row = blockIdx.x * 8 + wid;          // 0 .. 32767
    const float* src;
    __nv_bfloat16* dst;
    if (row < BATCH * L) {
        src = s1 + (size_t)row * D;
        dst = g_s1n + (size_t)row * D;
    } else {
        int r = row - BATCH * L;
        src = s2 + (size_t)r * D;
        dst = g_s2n + (size_t)r * D;
    }
    const float4* s4 = (const float4*)src;
    float4 v[6];
    float ss = 0.f;
    #pragma unroll
    for (int i = 0; i < 6; i++) {
        v[i] = s4[lane + 32 * i];
        ss += v[i].x * v[i].x + v[i].y * v[i].y + v[i].z * v[i].z + v[i].w * v[i].w;
    }
    #pragma unroll
    for (int o = 16; o > 0; o >>= 1) ss += __shfl_xor_sync(0xffffffffu, ss, o);
    float inv = rsqrtf(ss);
    #pragma unroll
    for (int i = 0; i < 6; i++) {
        __nv_bfloat162 a = __floats2bfloat162_rn(v[i].x * inv, v[i].y * inv);
        __nv_bfloat162 b = __floats2bfloat162_rn(v[i].z * inv, v[i].w * inv);
        uint2 pk;
        pk.x = *(const uint32_t*)&a;
        pk.y = *(const uint32_t*)&b;
        ((uint2*)dst)[lane + 32 * i] = pk;
    }
}

// ---------------------------------------------------------------------------
// Kernel 2: wmma bf16 GEMM — round-3 known-good config. CTA 128x128, BK=32,
// 8 warps (2Mx4N, 64x32 warp tile), 3-stage cp.async pipeline, LDA_S=48,
// NO minblocks cap (regs ~180, no spills). Epilogue: acc -> smem ->
// packed half uint4 stores of dist = 1 - dot into g_dskH.
// ---------------------------------------------------------------------------
#define BM 128
#define BN 128
#define BK 32
#define STAGES 3
#define NITER (D / BK)    // 24
#define LDA_S 48          // padded bf16 smem row (96 B)
#define LDC_S 132         // padded fp32 epi row
#define STAGE_ELEMS (BM * LDA_S)              // per matrix per stage (bf16)
#define STAGE_BYTES (2 * STAGE_ELEMS * 2)     // A+B per stage = 24576 B
#define SMEM_BYTES (STAGES * STAGE_BYTES)     // 73728 B (>= 128*132*4 epi)

__global__ __launch_bounds__(256) void gemm_dist_kernel() {
    extern __shared__ char smem[];
    __nv_bfloat16* sA[STAGES];
    __nv_bfloat16* sB[STAGES];
    #pragma unroll
    for (int s = 0; s < STAGES; s++) {
        sA[s] = (__nv_bfloat16*)(smem + s * STAGE_BYTES);
        sB[s] = sA[s] + STAGE_ELEMS;
    }

    int tid = threadIdx.x;
    int b  = blockIdx.z;
    int m0 = blockIdx.y * BM;
    int n0 = blockIdx.x * BN;
    const __nv_bfloat16* A  = g_s1n + (size_t)b * L * D;
    const __nv_bfloat16* Bm = g_s2n + (size_t)b * L * D;

    int warp = tid >> 5;
    int wm = warp & 1;        // 2 warps in M (64 rows)
    int wn = warp >> 1;       // 4 warps in N (32 cols)

    // load indices: chunk id = tid + it*256, row = id>>2, col = (id&3)*8
    int lr = tid >> 2;        // 0..63
    int lc = (tid & 3) * 8;

    wmma::fragment<wmma::accumulator, 16, 16, 16, float> acc[4][2];
    #pragma unroll
    for (int mi = 0; mi < 4; mi++)
        #pragma unroll
        for (int ni = 0; ni < 2; ni++)
            wmma::fill_fragment(acc[mi][ni], 0.0f);

    // prologue: stages 0, 1
    #pragma unroll
    for (int s = 0; s < 2; s++) {
        int k0 = s * BK;
        #pragma unroll
        for (int it = 0; it < 2; it++) {
            cp16(smem_u32(&sA[s][(lr + it * 64) * LDA_S + lc]),
                 A + (size_t)(m0 + lr + it * 64) * D + k0 + lc);
            cp16(smem_u32(&sB[s][(lr + it * 64) * LDA_S + lc]),
                 Bm + (size_t)(n0 + lr + it * 64) * D + k0 + lc);
        }
        CP_COMMIT();
    }

    for (int c = 0; c < NITER; c++) {
        CP_WAIT1();
        __syncthreads();
        int st = c % STAGES;

        #pragma unroll
        for (int kk = 0; kk < BK; kk += 16) {
            wmma::fragment<wmma::matrix_a, 16, 16, 16, __nv_bfloat16, wmma::row_major> af[4];
            wmma::fragment<wmma::matrix_b, 16, 16, 16, __nv_bfloat16, wmma::col_major> bf[2];
            #pragma unroll
            for (int mi = 0; mi < 4; mi++)
                wmma::load_matrix_sync(af[mi], &sA[st][(wm * 64 + mi * 16) * LDA_S + kk], LDA_S);
            #pragma unroll
            for (int ni = 0; ni < 2; ni++)
                wmma::load_matrix_sync(bf[ni], &sB[st][(wn * 32 + ni * 16) * LDA_S + kk], LDA_S);
            #pragma unroll
            for (int mi = 0; mi < 4; mi++)
                #pragma unroll
                for (int ni = 0; ni < 2; ni++)
                    wmma::mma_sync(acc[mi][ni], af[mi], bf[ni], acc[mi][ni]);
        }

        if (c + 2 < NITER) {
            int sn = (c + 2) % STAGES;
            int k0 = (c + 2) * BK;
            #pragma unroll
            for (int it = 0; it < 2; it++) {
                cp16(smem_u32(&sA[sn][(lr + it * 64) * LDA_S + lc]),
                     A + (size_t)(m0 + lr + it * 64) * D + k0 + lc);
                cp16(smem_u32(&sB[sn][(lr + it * 64) * LDA_S + lc]),
                     Bm + (size_t)(n0 + lr + it * 64) * D + k0 + lc);
            }
        }
        CP_COMMIT();
    }

    // epilogue: acc -> smem (reuse stages), packed half uint4 stores
    CP_WAIT0();
    __syncthreads();
    float* Cs = (float*)smem;
    #pragma unroll
    for (int mi = 0; mi < 4; mi++)
        #pragma unroll
        for (int ni = 0; ni < 2; ni++)
            wmma::store_matrix_sync(&Cs[(wm * 64 + mi * 16) * LDC_S + (wn * 32 + ni * 16)],
                                    acc[mi][ni], LDC_S, wmma::mem_row_major);
    __syncthreads();

    __half* dbase = g_dskH + (size_t)b * G2 * 2048;
    int jgl = tid & 31;           // local j group (4 cols), col = n0 + 4*jgl
    int sub = tid >> 5;           // 0..7

    #pragma unroll
    for (int it = 0; it < 8; it++) {
        int il2 = sub + it * 8;                      // local row pair 0..63
        float4 r0 = *(float4*)&Cs[(2 * il2)     * LDC_S + 4 * jgl];
        float4 r1 = *(float4*)&Cs[(2 * il2 + 1) * LDC_S + 4 * jgl];
        uint4 o;
        __half2* ph = (__half2*)&o;
        ph[0] = __floats2half2_rn(1.0f - r0.x, 1.0f - r0.y);
        ph[1] = __floats2half2_rn(1.0f - r0.z, 1.0f - r0.w);
        ph[2] = __floats2half2_rn(1.0f - r1.x, 1.0f - r1.y);
        ph[3] = __floats2half2_rn(1.0f - r1.z, 1.0f - r1.w);
        int g = (m0 >> 1) + il2 + (n0 >> 2) + jgl;
        *(uint4*)(dbase + (size_t)g * 2048 + ((n0 >> 2) + jgl) * 8) = o;
    }
}

// ---------------------------------------------------------------------------
// Kernel 3: DTW wavefront, barrier-free. 256 threads, thread jg owns cols
// [4jg,4jg+4), 2 rows per step, 768 steps. Warps pipeline via a full
// per-step boundary journal in smem + release/acquire progress counters;
// no __syncthreads inside the loop. Only lane 0 of each warp spins.
// ---------------------------------------------------------------------------
#define PF 8

__global__ __launch_bounds__(256) void dtw_kernel(float* __restrict__ out) {
    extern __shared__ float pubd[];                 // [8][768][2] = 49152 B
    __shared__ int prog[8];

    int b = blockIdx.x;
    int jg = threadIdx.x, lane = jg & 31, w = jg >> 5;

    if (jg < 8) prog[jg] = -1;
    __syncthreads();

    uint32_t my_prog   = smem_u32(&prog[w]);
    uint32_t prev_prog = smem_u32(&prog[w > 0 ? w - 1 : 0]);
    float* mypub   = pubd + (size_t)w * 768 * 2;
    const float* prevpub = pubd + (size_t)(w > 0 ? w - 1 : 0) * 768 * 2;

    const uint4* base = (const uint4*)(g_dskH + (size_t)b * G2 * 2048) + jg;
    // g row stride = 2048 halfs = 256 uint4

    float p0 = BIG, p1 = BIG, p2 = BIG, p3 = BIG;   // prev row of own 4 cols
    float c3r0 = BIG, c3r1 = BIG, prev_vb = BIG;
    float res = 0.0f;

    uint4 ring[PF];
    #pragma unroll
    for (int s = 0; s < PF; s++)
        ring[s] = base[(size_t)min(s, G2 - 1) * 256];

    #pragma unroll 4
    for (int S = 0; S < 768; S++) {
        uint4 u = ring[S & (PF - 1)];
        ring[S & (PF - 1)] = base[(size_t)min(S + PF, G2 - 1) * 256];

        float va = __shfl_up_sync(0xffffffffu, c3r0, 1);  // dtw[i0][4jg-1]
        float vb = __shfl_up_sync(0xffffffffu, c3r1, 1);  // dtw[i0+1][4jg-1]
        if (lane == 0) {
            va = BIG; vb = BIG;
            if (w > 0 && S > 0) {
                while (ld_acquire_cta(prev_prog) < S - 1) { }
                va = prevpub[(S - 1) * 2 + 0];
                vb = prevpub[(S - 1) * 2 + 1];
            }
        }

        int i0 = 2 * (S - jg);
        if ((unsigned)i0 < 1024u) {
            float2 q0 = __half22float2(((const __half2*)&u)[0]);
            float2 q1 = __half22float2(((const __half2*)&u)[1]);
            float2 q2 = __half22float2(((const __half2*)&u)[2]);
            float2 q3 = __half22float2(((const __half2*)&u)[3]);
            // row i0 (min-plus prefix form)
            float D0 = q0.x, D1 = D0 + q0.y, D2 = D1 + q1.x, D3 = D2 + q1.y;
            float f0 = fminf(prev_vb, p0);
            float f1 = fminf(p0, p1) - D0;
            float f2 = fminf(p1, p2) - D1;
            float f3 = fminf(p2, p3) - D2;
            float m0 = fminf(va, f0);
            if (i0 == 0 && jg == 0) m0 = 0.0f;
            float m1 = fminf(m0, f1);
            float m2 = fminf(m1, f2);
            float m3 = fminf(m2, f3);
            float c0 = D0 + m0, c1 = D1 + m1, c2 = D2 + m2, c3 = D3 + m3;
            // row i0+1
            float E0 = q2.x, E1 = E0 + q2.y, E2 = E1 + q3.x, E3 = E2 + q3.y;
            float h0 = fminf(va, c0);
            float h1 = fminf(c0, c1) - E0;
            float h2 = fminf(c1, c2) - E1;
            float h3 = fminf(c2, c3) - E2;
            float n0 = fminf(vb, h0);
            float n1 = fminf(n0, h1);
            float n2 = fminf(n1, h2);
            float n3 = fminf(n2, h3);
            p0 = E0 + n0; p1 = E1 + n1; p2 = E2 + n2; p3 = E3 + n3;
            c3r0 = c3; c3r1 = p3;
            if (i0 == 1022 && jg == 255) res = p3;
        }
        prev_vb = vb;
        if (lane == 31 && w < 7) {
            mypub[S * 2 + 0] = c3r0;
            mypub[S * 2 + 1] = c3r1;
            st_release_cta(my_prog, S);
        }
    }

    if (jg == 255)
        out[b] = 1.0f / (1.0f + res * (1.0f / 2048.0f));
}

// ---------------------------------------------------------------------------
extern "C" void kernel_launch(void* const* d_in, const int* in_sizes, int n_in,
                              void* d_out, int out_size) {
    const float* s1 = (const float*)d_in[0];
    const float* s2 = (const float*)d_in[1];
    float* out = (float*)d_out;

    cudaFuncSetAttribute(gemm_dist_kernel,
                         cudaFuncAttributeMaxDynamicSharedMemorySize, SMEM_BYTES);
    cudaFuncSetAttribute(dtw_kernel,
                         cudaFuncAttributeMaxDynamicSharedMemorySize, 8 * 768 * 2 * 4);

    normalize_kernel<<<4096, 256>>>(s1, s2);
    gemm_dist_kernel<<<dim3(L / BN, L / BM, BATCH), 256, SMEM_BYTES>>>();
    dtw_kernel<<<BATCH, 256, 8 * 768 * 2 * 4>>>(out);
}

// round 7
// speedup vs baseline: 3.3058x; 3.2864x over previous
#include <cuda_runtime.h>
#include <cuda_bf16.h>
#include <cuda_fp16.h>
#include <mma.h>
#include <cstdint>

using namespace nvcuda;

#define BATCH 16
#define L 1024
#define D 768
#define G2 768            // group rows per batch (max g = 511+255 = 766)
#define BIG 1e30f

// -------- device scratch (allocation-free rule: __device__ globals) --------
__device__ __nv_bfloat16 g_s1n[BATCH * L * D];                 // 25 MB
__device__ __nv_bfloat16 g_s2n[BATCH * L * D];                 // 25 MB
// dist (=1-dot) as half, DTW-step layout: cell (i,j) ->
// g_dskH[b][g][jg][r][c], g = i/2 + j/4, jg = j/4, r = i&1, c = j&3.
__device__ __half g_dskH[(size_t)BATCH * G2 * 2048];           // 48 MB

// ---------------------------------------------------------------------------
// helpers
// ---------------------------------------------------------------------------
__device__ __forceinline__ uint32_t smem_u32(const void* p) {
    uint32_t a;
    asm("{ .reg .u64 t; cvta.to.shared.u64 t, %1; cvt.u32.u64 %0, t; }"
        : "=r"(a) : "l"(p));
    return a;
}
__device__ __forceinline__ void cp16(uint32_t dst, const void* src) {
    asm volatile("cp.async.cg.shared.global [%0], [%1], 16;"
                 :: "r"(dst), "l"(src) : "memory");
}
#define CP_COMMIT() asm volatile("cp.async.commit_group;" ::: "memory")
#define CP_WAIT1()  asm volatile("cp.async.wait_group 1;" ::: "memory")
#define CP_WAIT0()  asm volatile("cp.async.wait_group 0;" ::: "memory")

// ---------------------------------------------------------------------------
// Kernel 1: L2-normalize. One warp per row, float4 loads, shfl reduction.
// ---------------------------------------------------------------------------
__global__ __launch_bounds__(256) void normalize_kernel(const float* __restrict__ s1,
                                                        const float* __restrict__ s2) {
    int wid = threadIdx.x >> 5, lane = threadIdx.x & 31;
    int row = blockIdx.x * 8 + wid;          // 0 .. 32767
    const float* src;
    __nv_bfloat16* dst;
    if (row < BATCH * L) {
        src = s1 + (size_t)row * D;
        dst = g_s1n + (size_t)row * D;
    } else {
        int r = row - BATCH * L;
        src = s2 + (size_t)r * D;
        dst = g_s2n + (size_t)r * D;
    }
    const float4* s4 = (const float4*)src;
    float4 v[6];
    float ss = 0.f;
    #pragma unroll
    for (int i = 0; i < 6; i++) {
        v[i] = s4[lane + 32 * i];
        ss += v[i].x * v[i].x + v[i].y * v[i].y + v[i].z * v[i].z + v[i].w * v[i].w;
    }
    #pragma unroll
    for (int o = 16; o > 0; o >>= 1) ss += __shfl_xor_sync(0xffffffffu, ss, o);
    float inv = rsqrtf(ss);
    #pragma unroll
    for (int i = 0; i < 6; i++) {
        __nv_bfloat162 a = __floats2bfloat162_rn(v[i].x * inv, v[i].y * inv);
        __nv_bfloat162 b = __floats2bfloat162_rn(v[i].z * inv, v[i].w * inv);
        uint2 pk;
        pk.x = *(const uint32_t*)&a;
        pk.y = *(const uint32_t*)&b;
        ((uint2*)dst)[lane + 32 * i] = pk;
    }
}

// ---------------------------------------------------------------------------
// Kernel 2: wmma bf16 GEMM. CTA 128x128, BK=32, 8 warps (2Mx4N, 64x32 warp
// tile), 3-stage cp.async pipeline, LDA_S=48, no occupancy cap.
// Fragment-level software pipelining: load k16=0 frags, issue next-stage
// cp.asyncs, load k16=1 frags, then both MMA batches (loads overlap MMAs).
// Epilogue: acc -> smem -> packed half uint4 stores of 1 - dot into g_dskH.
// ---------------------------------------------------------------------------
#define BM 128
#define BN 128
#define BK 32
#define STAGES 3
#define NITER (D / BK)    // 24
#define LDA_S 48          // padded bf16 smem row (96 B)
#define LDC_S 132         // padded fp32 epi row
#define STAGE_ELEMS (BM * LDA_S)              // per matrix per stage (bf16)
#define STAGE_BYTES (2 * STAGE_ELEMS * 2)     // A+B per stage = 24576 B
#define SMEM_BYTES (STAGES * STAGE_BYTES)     // 73728 B (>= 128*132*4 epi)

typedef wmma::fragment<wmma::matrix_a, 16, 16, 16, __nv_bfloat16, wmma::row_major> FragA;
typedef wmma::fragment<wmma::matrix_b, 16, 16, 16, __nv_bfloat16, wmma::col_major> FragB;

__global__ __launch_bounds__(256) void gemm_dist_kernel() {
    extern __shared__ char smem[];
    __nv_bfloat16* sA[STAGES];
    __nv_bfloat16* sB[STAGES];
    #pragma unroll
    for (int s = 0; s < STAGES; s++) {
        sA[s] = (__nv_bfloat16*)(smem + s * STAGE_BYTES);
        sB[s] = sA[s] + STAGE_ELEMS;
    }

    int tid = threadIdx.x;
    int b  = blockIdx.z;
    int m0 = blockIdx.y * BM;
    int n0 = blockIdx.x * BN;
    const __nv_bfloat16* A  = g_s1n + (size_t)b * L * D;
    const __nv_bfloat16* Bm = g_s2n + (size_t)b * L * D;

    int warp = tid >> 5;
    int wm = warp & 1;        // 2 warps in M (64 rows)
    int wn = warp >> 1;       // 4 warps in N (32 cols)

    // load indices: chunk id = tid + it*256, row = id>>2, col = (id&3)*8
    int lr = tid >> 2;        // 0..63
    int lc = (tid & 3) * 8;

    wmma::fragment<wmma::accumulator, 16, 16, 16, float> acc[4][2];
    #pragma unroll
    for (int mi = 0; mi < 4; mi++)
        #pragma unroll
        for (int ni = 0; ni < 2; ni++)
            wmma::fill_fragment(acc[mi][ni], 0.0f);

    // prologue: stages 0, 1
    #pragma unroll
    for (int s = 0; s < 2; s++) {
        int k0 = s * BK;
        #pragma unroll
        for (int it = 0; it < 2; it++) {
            cp16(smem_u32(&sA[s][(lr + it * 64) * LDA_S + lc]),
                 A + (size_t)(m0 + lr + it * 64) * D + k0 + lc);
            cp16(smem_u32(&sB[s][(lr + it * 64) * LDA_S + lc]),
                 Bm + (size_t)(n0 + lr + it * 64) * D + k0 + lc);
        }
        CP_COMMIT();
    }

    #pragma unroll 3
    for (int c = 0; c < NITER; c++) {
        CP_WAIT1();
        __syncthreads();
        int st = c % STAGES;

        FragA af[2][4];
        FragB bf[2][2];

        // k16 = 0 fragments
        #pragma unroll
        for (int mi = 0; mi < 4; mi++)
            wmma::load_matrix_sync(af[0][mi], &sA[st][(wm * 64 + mi * 16) * LDA_S], LDA_S);
        #pragma unroll
        for (int ni = 0; ni < 2; ni++)
            wmma::load_matrix_sync(bf[0][ni], &sB[st][(wn * 32 + ni * 16) * LDA_S], LDA_S);

        // issue next-stage global prefetch early (stage (c-1)%3 is dead here)
        if (c + 2 < NITER) {
            int sn = (c + 2) % STAGES;
            int k0 = (c + 2) * BK;
            #pragma unroll
            for (int it = 0; it < 2; it++) {
                cp16(smem_u32(&sA[sn][(lr + it * 64) * LDA_S + lc]),
                     A + (size_t)(m0 + lr + it * 64) * D + k0 + lc);
                cp16(smem_u32(&sB[sn][(lr + it * 64) * LDA_S + lc]),
                     Bm + (size_t)(n0 + lr + it * 64) * D + k0 + lc);
            }
        }
        CP_COMMIT();

        // k16 = 1 fragments (overlap with first MMA batch below via scheduler)
        #pragma unroll
        for (int mi = 0; mi < 4; mi++)
            wmma::load_matrix_sync(af[1][mi], &sA[st][(wm * 64 + mi * 16) * LDA_S + 16], LDA_S);
        #pragma unroll
        for (int ni = 0; ni < 2; ni++)
            wmma::load_matrix_sync(bf[1][ni], &sB[st][(wn * 32 + ni * 16) * LDA_S + 16], LDA_S);

        #pragma unroll
        for (int k16 = 0; k16 < 2; k16++)
            #pragma unroll
            for (int mi = 0; mi < 4; mi++)
                #pragma unroll
                for (int ni = 0; ni < 2; ni++)
                    wmma::mma_sync(acc[mi][ni], af[k16][mi], bf[k16][ni], acc[mi][ni]);
    }

    // epilogue: acc -> smem (reuse stages), packed half uint4 stores
    CP_WAIT0();
    __syncthreads();
    float* Cs = (float*)smem;
    #pragma unroll
    for (int mi = 0; mi < 4; mi++)
        #pragma unroll
        for (int ni = 0; ni < 2; ni++)
            wmma::store_matrix_sync(&Cs[(wm * 64 + mi * 16) * LDC_S + (wn * 32 + ni * 16)],
                                    acc[mi][ni], LDC_S, wmma::mem_row_major);
    __syncthreads();

    __half* dbase = g_dskH + (size_t)b * G2 * 2048;
    int jgl = tid & 31;           // local j group (4 cols), col = n0 + 4*jgl
    int sub = tid >> 5;           // 0..7

    #pragma unroll
    for (int it = 0; it < 8; it++) {
        int il2 = sub + it * 8;                      // local row pair 0..63
        float4 r0 = *(float4*)&Cs[(2 * il2)     * LDC_S + 4 * jgl];
        float4 r1 = *(float4*)&Cs[(2 * il2 + 1) * LDC_S + 4 * jgl];
        uint4 o;
        __half2* ph = (__half2*)&o;
        ph[0] = __floats2half2_rn(1.0f - r0.x, 1.0f - r0.y);
        ph[1] = __floats2half2_rn(1.0f - r0.z, 1.0f - r0.w);
        ph[2] = __floats2half2_rn(1.0f - r1.x, 1.0f - r1.y);
        ph[3] = __floats2half2_rn(1.0f - r1.z, 1.0f - r1.w);
        int g = (m0 >> 1) + il2 + (n0 >> 2) + jgl;
        *(uint4*)(dbase + (size_t)g * 2048 + ((n0 >> 2) + jgl) * 8) = o;
    }
}

// ---------------------------------------------------------------------------
// Kernel 3: DTW wavefront (round-4 proven version). 256 threads, thread jg
// owns cols [4jg,4jg+4), 2 rows per macro-step, 768 steps. One uint4 (8 half)
// dist load per thread per step, min-plus prefix form. Neighbor handoff via
// shfl + parity double-buffered smem; one __syncthreads per step.
// ---------------------------------------------------------------------------
#define PF 8

__global__ __launch_bounds__(256) void dtw_kernel(float* __restrict__ out) {
    int b = blockIdx.x;
    int jg = threadIdx.x, lane = jg & 31, w = jg >> 5;

    const uint4* base = (const uint4*)(g_dskH + (size_t)b * G2 * 2048) + jg;
    // g row stride = 2048 halfs = 256 uint4

    __shared__ float pub[2][8][2];
    if (lane < 2) { pub[0][w][lane] = BIG; pub[1][w][lane] = BIG; }
    __syncthreads();

    float p0 = BIG, p1 = BIG, p2 = BIG, p3 = BIG;   // prev row of own 4 cols
    float c3r0 = BIG, c3r1 = BIG, prev_vb = BIG;
    float res = 0.0f;

    uint4 ring[PF];
    #pragma unroll
    for (int s = 0; s < PF; s++)
        ring[s] = base[(size_t)min(s, G2 - 1) * 256];

    #pragma unroll 8
    for (int S = 0; S < 768; S++) {
        uint4 u = ring[S & (PF - 1)];
        ring[S & (PF - 1)] = base[(size_t)min(S + PF, G2 - 1) * 256];

        float va = __shfl_up_sync(0xffffffffu, c3r0, 1);  // dtw[i0][4jg-1]
        float vb = __shfl_up_sync(0xffffffffu, c3r1, 1);  // dtw[i0+1][4jg-1]
        if (lane == 0) {
            if (w > 0) {
                va = pub[(S & 1) ^ 1][w - 1][0];
                vb = pub[(S & 1) ^ 1][w - 1][1];
            } else { va = BIG; vb = BIG; }
        }

        int i0 = 2 * (S - jg);
        if ((unsigned)i0 < 1024u) {
            float2 q0 = __half22float2(((const __half2*)&u)[0]);
            float2 q1 = __half22float2(((const __half2*)&u)[1]);
            float2 q2 = __half22float2(((const __half2*)&u)[2]);
            float2 q3 = __half22float2(((const __half2*)&u)[3]);
            // row i0 (min-plus prefix form)
            float D0 = q0.x, D1 = D0 + q0.y, D2 = D1 + q1.x, D3 = D2 + q1.y;
            float f0 = fminf(prev_vb, p0);
            float f1 = fminf(p0, p1) - D0;
            float f2 = fminf(p1, p2) - D1;
            float f3 = fminf(p2, p3) - D2;
            float m0 = fminf(va, f0);
            if (i0 == 0 && jg == 0) m0 = 0.0f;
            float m1 = fminf(m0, f1);
            float m2 = fminf(m1, f2);
            float m3 = fminf(m2, f3);
            float c0 = D0 + m0, c1 = D1 + m1, c2 = D2 + m2, c3 = D3 + m3;
            // row i0+1
            float E0 = q2.x, E1 = E0 + q2.y, E2 = E1 + q3.x, E3 = E2 + q3.y;
            float h0 = fminf(va, c0);
            float h1 = fminf(c0, c1) - E0;
            float h2 = fminf(c1, c2) - E1;
            float h3 = fminf(c2, c3) - E2;
            float n0 = fminf(vb, h0);
            float n1 = fminf(n0, h1);
            float n2 = fminf(n1, h2);
            float n3 = fminf(n2, h3);
            p0 = E0 + n0; p1 = E1 + n1; p2 = E2 + n2; p3 = E3 + n3;
            c3r0 = c3; c3r1 = p3;
            if (i0 == 1022 && jg == 255) res = p3;
        }
        prev_vb = vb;
        if (lane == 31) { pub[S & 1][w][0] = c3r0; pub[S & 1][w][1] = c3r1; }
        __syncthreads();
    }

    if (jg == 255)
        out[b] = 1.0f / (1.0f + res * (1.0f / 2048.0f));
}

// ---------------------------------------------------------------------------
extern "C" void kernel_launch(void* const* d_in, const int* in_sizes, int n_in,
                              void* d_out, int out_size) {
    const float* s1 = (const float*)d_in[0];
    const float* s2 = (const float*)d_in[1];
    float* out = (float*)d_out;

    cudaFuncSetAttribute(gemm_dist_kernel,
                         cudaFuncAttributeMaxDynamicSharedMemorySize, SMEM_BYTES);

    normalize_kernel<<<4096, 256>>>(s1, s2);
    gemm_dist_kernel<<<dim3(L / BN, L / BM, BATCH), 256, SMEM_BYTES>>>();
    dtw_kernel<<<BATCH, 256>>>(out);
}

// round 8
// speedup vs baseline: 4.0979x; 1.2396x over previous
#include <cuda_runtime.h>
#include <cuda_fp16.h>
#include <mma.h>
#include <cstdint>

using namespace nvcuda;

#define BATCH 16
#define L 1024
#define D 768
#define G2 768            // group rows per batch (max g = 511+255 = 766)
#define BIG 1e30f

// -------- device scratch (allocation-free rule: __device__ globals) --------
__device__ signed char g_q1[BATCH * L * D];                    // 12.6 MB
__device__ signed char g_q2[BATCH * L * D];                    // 12.6 MB
__device__ float g_sc1[BATCH * L];                             // per-row scale
__device__ float g_sc2[BATCH * L];
// dist (=1-cos) as half, DTW-step layout: cell (i,j) ->
// g_dskH[b][g][jg][r][c], g = i/2 + j/4, jg = j/4, r = i&1, c = j&3.
__device__ __half g_dskH[(size_t)BATCH * G2 * 2048];           // 48 MB

// ---------------------------------------------------------------------------
// helpers
// ---------------------------------------------------------------------------
__device__ __forceinline__ uint32_t smem_u32(const void* p) {
    uint32_t a;
    asm("{ .reg .u64 t; cvta.to.shared.u64 t, %1; cvt.u32.u64 %0, t; }"
        : "=r"(a) : "l"(p));
    return a;
}
__device__ __forceinline__ void cp16(uint32_t dst, const void* src) {
    asm volatile("cp.async.cg.shared.global [%0], [%1], 16;"
                 :: "r"(dst), "l"(src) : "memory");
}
#define CP_COMMIT() asm volatile("cp.async.commit_group;" ::: "memory")
#define CP_WAIT1()  asm volatile("cp.async.wait_group 1;" ::: "memory")
#define CP_WAIT0()  asm volatile("cp.async.wait_group 0;" ::: "memory")

// ---------------------------------------------------------------------------
// Kernel 1: L2-normalize + int8 quantize. One warp per row.
// q = round(v * 127 / max|v|)  (norm cancels);  scale = max|v| / (127*||v||)
// ---------------------------------------------------------------------------
__global__ __launch_bounds__(256) void normalize_kernel(const float* __restrict__ s1,
                                                        const float* __restrict__ s2) {
    int wid = threadIdx.x >> 5, lane = threadIdx.x & 31;
    int row = blockIdx.x * 8 + wid;          // 0 .. 32767
    const float* src;
    signed char* dst;
    float* scp;
    int srow;
    if (row < BATCH * L) {
        srow = row;
        src = s1 + (size_t)srow * D;
        dst = g_q1 + (size_t)srow * D;
        scp = g_sc1 + srow;
    } else {
        srow = row - BATCH * L;
        src = s2 + (size_t)srow * D;
        dst = g_q2 + (size_t)srow * D;
        scp = g_sc2 + srow;
    }
    const float4* s4 = (const float4*)src;
    float4 v[6];
    float ss = 0.f, mx = 0.f;
    #pragma unroll
    for (int i = 0; i < 6; i++) {
        v[i] = s4[lane + 32 * i];
        ss += v[i].x * v[i].x + v[i].y * v[i].y + v[i].z * v[i].z + v[i].w * v[i].w;
        mx = fmaxf(mx, fmaxf(fmaxf(fabsf(v[i].x), fabsf(v[i].y)),
                             fmaxf(fabsf(v[i].z), fabsf(v[i].w))));
    }
    #pragma unroll
    for (int o = 16; o > 0; o >>= 1) {
        ss += __shfl_xor_sync(0xffffffffu, ss, o);
        mx = fmaxf(mx, __shfl_xor_sync(0xffffffffu, mx, o));
    }
    float qmul = 127.0f / mx;
    if (lane == 0)
        *scp = mx * rsqrtf(ss) * (1.0f / 127.0f);
    #pragma unroll
    for (int i = 0; i < 6; i++) {
        char4 c;
        c.x = (signed char)__float2int_rn(v[i].x * qmul);
        c.y = (signed char)__float2int_rn(v[i].y * qmul);
        c.z = (signed char)__float2int_rn(v[i].z * qmul);
        c.w = (signed char)__float2int_rn(v[i].w * qmul);
        ((char4*)dst)[lane + 32 * i] = c;
    }
}

// ---------------------------------------------------------------------------
// Kernel 2: int8 wmma GEMM (IMMA). CTA 128x128, BK=64 (64B rows), 8 warps
// (2Mx4N, 64x32 warp tile), 3-stage cp.async, LDQ=80 (conflict-free).
// Epilogue: int acc -> smem -> dist = 1 - acc*s1[i]*s2[j] -> packed half
// uint4 stores into g_dskH skewed layout.
// ---------------------------------------------------------------------------
#define BM 128
#define BN 128
#define BKI 64
#define STAGES 3
#define NITERI (D / BKI)    // 12
#define LDQ 80              // int8 smem row stride (bytes); 80r mod 128 distinct
#define LDC_S 132           // padded int32 epi row
#define STAGE_BYTES (2 * BM * LDQ)            // A+B per stage = 20480 B
#define SMEM_BYTES (128 * LDC_S * 4)          // 67584 B  (> 3*20480 = 61440)

typedef wmma::fragment<wmma::matrix_a, 16, 16, 16, signed char, wmma::row_major> FragAi;
typedef wmma::fragment<wmma::matrix_b, 16, 16, 16, signed char, wmma::col_major> FragBi;
typedef wmma::fragment<wmma::accumulator, 16, 16, 16, int> FragCi;

__global__ __launch_bounds__(256) void gemm_dist_kernel() {
    extern __shared__ char smem[];
    signed char* sA[STAGES];
    signed char* sB[STAGES];
    #pragma unroll
    for (int s = 0; s < STAGES; s++) {
        sA[s] = (signed char*)(smem + s * STAGE_BYTES);
        sB[s] = sA[s] + BM * LDQ;
    }
    __shared__ float s1s[128], s2s[128];

    int tid = threadIdx.x;
    int b  = blockIdx.z;
    int m0 = blockIdx.y * BM;
    int n0 = blockIdx.x * BN;
    const signed char* A  = g_q1 + (size_t)b * L * D;
    const signed char* Bm = g_q2 + (size_t)b * L * D;

    int warp = tid >> 5;
    int wm = warp & 1;        // 2 warps in M (64 rows)
    int wn = warp >> 1;       // 4 warps in N (32 cols)

    // load indices: chunk id = tid + it*256 (0..511), row = id>>2, col=(id&3)*16
    int lr = tid >> 2;        // 0..63
    int lc = (tid & 3) * 16;

    FragCi acc[4][2];
    #pragma unroll
    for (int mi = 0; mi < 4; mi++)
        #pragma unroll
        for (int ni = 0; ni < 2; ni++)
            wmma::fill_fragment(acc[mi][ni], 0);

    // prologue: stages 0, 1
    #pragma unroll
    for (int s = 0; s < 2; s++) {
        int k0 = s * BKI;
        #pragma unroll
        for (int it = 0; it < 2; it++) {
            cp16(smem_u32(&sA[s][(lr + it * 64) * LDQ + lc]),
                 A + (size_t)(m0 + lr + it * 64) * D + k0 + lc);
            cp16(smem_u32(&sB[s][(lr + it * 64) * LDQ + lc]),
                 Bm + (size_t)(n0 + lr + it * 64) * D + k0 + lc);
        }
        CP_COMMIT();
    }

    for (int c = 0; c < NITERI; c++) {
        CP_WAIT1();
        __syncthreads();
        int st = c % STAGES;

        #pragma unroll
        for (int kk = 0; kk < BKI; kk += 16) {
            FragAi af[4];
            FragBi bf[2];
            #pragma unroll
            for (int mi = 0; mi < 4; mi++)
                wmma::load_matrix_sync(af[mi], &sA[st][(wm * 64 + mi * 16) * LDQ + kk], LDQ);
            #pragma unroll
            for (int ni = 0; ni < 2; ni++)
                wmma::load_matrix_sync(bf[ni], &sB[st][(wn * 32 + ni * 16) * LDQ + kk], LDQ);
            #pragma unroll
            for (int mi = 0; mi < 4; mi++)
                #pragma unroll
                for (int ni = 0; ni < 2; ni++)
                    wmma::mma_sync(acc[mi][ni], af[mi], bf[ni], acc[mi][ni]);
        }

        if (c + 2 < NITERI) {
            int sn = (c + 2) % STAGES;
            int k0 = (c + 2) * BKI;
            #pragma unroll
            for (int it = 0; it < 2; it++) {
                cp16(smem_u32(&sA[sn][(lr + it * 64) * LDQ + lc]),
                     A + (size_t)(m0 + lr + it * 64) * D + k0 + lc);
                cp16(smem_u32(&sB[sn][(lr + it * 64) * LDQ + lc]),
                     Bm + (size_t)(n0 + lr + it * 64) * D + k0 + lc);
            }
        }
        CP_COMMIT();
    }

    // epilogue: int acc -> smem, rescale, packed half uint4 stores
    CP_WAIT0();
    __syncthreads();
    if (tid < 128) {
        s1s[tid] = g_sc1[b * L + m0 + tid];
        s2s[tid] = g_sc2[b * L + n0 + tid];
    }
    int* CsI = (int*)smem;
    #pragma unroll
    for (int mi = 0; mi < 4; mi++)
        #pragma unroll
        for (int ni = 0; ni < 2; ni++)
            wmma::store_matrix_sync(&CsI[(wm * 64 + mi * 16) * LDC_S + (wn * 32 + ni * 16)],
                                    acc[mi][ni], LDC_S, wmma::mem_row_major);
    __syncthreads();

    __half* dbase = g_dskH + (size_t)b * G2 * 2048;
    int jgl = tid & 31;           // local j group (4 cols), col = n0 + 4*jgl
    int sub = tid >> 5;           // 0..7

    float sb0 = s2s[4 * jgl], sb1 = s2s[4 * jgl + 1];
    float sb2 = s2s[4 * jgl + 2], sb3 = s2s[4 * jgl + 3];

    #pragma unroll
    for (int it = 0; it < 8; it++) {
        int il2 = sub + it * 8;                      // local row pair 0..63
        int4 r0 = *(int4*)&CsI[(2 * il2)     * LDC_S + 4 * jgl];
        int4 r1 = *(int4*)&CsI[(2 * il2 + 1) * LDC_S + 4 * jgl];
        float sa0 = s1s[2 * il2], sa1 = s1s[2 * il2 + 1];
        uint4 o;
        __half2* ph = (__half2*)&o;
        ph[0] = __floats2half2_rn(1.0f - (float)r0.x * sa0 * sb0,
                                  1.0f - (float)r0.y * sa0 * sb1);
        ph[1] = __floats2half2_rn(1.0f - (float)r0.z * sa0 * sb2,
                                  1.0f - (float)r0.w * sa0 * sb3);
        ph[2] = __floats2half2_rn(1.0f - (float)r1.x * sa1 * sb0,
                                  1.0f - (float)r1.y * sa1 * sb1);
        ph[3] = __floats2half2_rn(1.0f - (float)r1.z * sa1 * sb2,
                                  1.0f - (float)r1.w * sa1 * sb3);
        int g = (m0 >> 1) + il2 + (n0 >> 2) + jgl;
        *(uint4*)(dbase + (size_t)g * 2048 + ((n0 >> 2) + jgl) * 8) = o;
    }
}

// ---------------------------------------------------------------------------
// Kernel 3: DTW wavefront (round-4 proven version). 256 threads, thread jg
// owns cols [4jg,4jg+4), 2 rows per macro-step, 768 steps. One uint4 (8 half)
// dist load per thread per step, min-plus prefix form. Neighbor handoff via
// shfl + parity double-buffered smem; one __syncthreads per step.
// ---------------------------------------------------------------------------
#define PF 8

__global__ __launch_bounds__(256) void dtw_kernel(float* __restrict__ out) {
    int b = blockIdx.x;
    int jg = threadIdx.x, lane = jg & 31, w = jg >> 5;

    const uint4* base = (const uint4*)(g_dskH + (size_t)b * G2 * 2048) + jg;
    // g row stride = 2048 halfs = 256 uint4

    __shared__ float pub[2][8][2];
    if (lane < 2) { pub[0][w][lane] = BIG; pub[1][w][lane] = BIG; }
    __syncthreads();

    float p0 = BIG, p1 = BIG, p2 = BIG, p3 = BIG;   // prev row of own 4 cols
    float c3r0 = BIG, c3r1 = BIG, prev_vb = BIG;
    float res = 0.0f;

    uint4 ring[PF];
    #pragma unroll
    for (int s = 0; s < PF; s++)
        ring[s] = base[(size_t)min(s, G2 - 1) * 256];

    #pragma unroll 8
    for (int S = 0; S < 768; S++) {
        uint4 u = ring[S & (PF - 1)];
        ring[S & (PF - 1)] = base[(size_t)min(S + PF, G2 - 1) * 256];

        float va = __shfl_up_sync(0xffffffffu, c3r0, 1);  // dtw[i0][4jg-1]
        float vb = __shfl_up_sync(0xffffffffu, c3r1, 1);  // dtw[i0+1][4jg-1]
        if (lane == 0) {
            if (w > 0) {
                va = pub[(S & 1) ^ 1][w - 1][0];
                vb = pub[(S & 1) ^ 1][w - 1][1];
            } else { va = BIG; vb = BIG; }
        }

        int i0 = 2 * (S - jg);
        if ((unsigned)i0 < 1024u) {
            float2 q0 = __half22float2(((const __half2*)&u)[0]);
            float2 q1 = __half22float2(((const __half2*)&u)[1]);
            float2 q2 = __half22float2(((const __half2*)&u)[2]);
            float2 q3 = __half22float2(((const __half2*)&u)[3]);
            // row i0 (min-plus prefix form)
            float D0 = q0.x, D1 = D0 + q0.y, D2 = D1 + q1.x, D3 = D2 + q1.y;
            float f0 = fminf(prev_vb, p0);
            float f1 = fminf(p0, p1) - D0;
            float f2 = fminf(p1, p2) - D1;
            float f3 = fminf(p2, p3) - D2;
            float m0 = fminf(va, f0);
            if (i0 == 0 && jg == 0) m0 = 0.0f;
            float m1 = fminf(m0, f1);
            float m2 = fminf(m1, f2);
            float m3 = fminf(m2, f3);
            float c0 = D0 + m0, c1 = D1 + m1, c2 = D2 + m2, c3 = D3 + m3;
            // row i0+1
            float E0 = q2.x, E1 = E0 + q2.y, E2 = E1 + q3.x, E3 = E2 + q3.y;
            float h0 = fminf(va, c0);
            float h1 = fminf(c0, c1) - E0;
            float h2 = fminf(c1, c2) - E1;
            float h3 = fminf(c2, c3) - E2;
            float n0 = fminf(vb, h0);
            float n1 = fminf(n0, h1);
            float n2 = fminf(n1, h2);
            float n3 = fminf(n2, h3);
            p0 = E0 + n0; p1 = E1 + n1; p2 = E2 + n2; p3 = E3 + n3;
            c3r0 = c3; c3r1 = p3;
            if (i0 == 1022 && jg == 255) res = p3;
        }
        prev_vb = vb;
        if (lane == 31) { pub[S & 1][w][0] = c3r0; pub[S & 1][w][1] = c3r1; }
        __syncthreads();
    }

    if (jg == 255)
        out[b] = 1.0f / (1.0f + res * (1.0f / 2048.0f));
}

// ---------------------------------------------------------------------------
extern "C" void kernel_launch(void* const* d_in, const int* in_sizes, int n_in,
                              void* d_out, int out_size) {
    const float* s1 = (const float*)d_in[0];
    const float* s2 = (const float*)d_in[1];
    float* out = (float*)d_out;

    cudaFuncSetAttribute(gemm_dist_kernel,
                         cudaFuncAttributeMaxDynamicSharedMemorySize, SMEM_BYTES);

    normalize_kernel<<<4096, 256>>>(s1, s2);
    gemm_dist_kernel<<<dim3(L / BN, L / BM, BATCH), 256, SMEM_BYTES>>>();
    dtw_kernel<<<BATCH, 256>>>(out);
}

// round 9
// speedup vs baseline: 4.5182x; 1.1026x over previous
#include <cuda_runtime.h>
#include <cuda_fp16.h>
#include <cstdint>

#define BATCH 16
#define L 1024
#define D 768
#define G2 768            // group rows per batch (max g = 511+255 = 766)
#define BIG 1e30f

// -------- device scratch (allocation-free rule: __device__ globals) --------
__device__ signed char g_q1[BATCH * L * D];                    // 12.6 MB
__device__ signed char g_q2[BATCH * L * D];                    // 12.6 MB
__device__ float g_sc1[BATCH * L];                             // per-row scale
__device__ float g_sc2[BATCH * L];
// dist (=1-cos) as half, DTW-step layout: cell (i,j) ->
// g_dskH[b][g][jg][r][c], g = i/2 + j/4, jg = j/4, r = i&1, c = j&3.
__device__ __half g_dskH[(size_t)BATCH * G2 * 2048];           // 48 MB

// ---------------------------------------------------------------------------
// helpers
// ---------------------------------------------------------------------------
__device__ __forceinline__ uint32_t smem_u32(const void* p) {
    uint32_t a;
    asm("{ .reg .u64 t; cvta.to.shared.u64 t, %1; cvt.u32.u64 %0, t; }"
        : "=r"(a) : "l"(p));
    return a;
}
__device__ __forceinline__ void cp16(uint32_t dst, const void* src) {
    asm volatile("cp.async.cg.shared.global [%0], [%1], 16;"
                 :: "r"(dst), "l"(src) : "memory");
}
#define CP_COMMIT() asm volatile("cp.async.commit_group;" ::: "memory")
#define CP_WAIT1()  asm volatile("cp.async.wait_group 1;" ::: "memory")
#define CP_WAIT0()  asm volatile("cp.async.wait_group 0;" ::: "memory")

__device__ __forceinline__ void mma_s8_16832(int* c, const uint32_t* a, const uint32_t* b) {
    asm volatile(
        "mma.sync.aligned.m16n8k32.row.col.s32.s8.s8.s32 "
        "{%0,%1,%2,%3}, {%4,%5,%6,%7}, {%8,%9}, {%0,%1,%2,%3};"
        : "+r"(c[0]), "+r"(c[1]), "+r"(c[2]), "+r"(c[3])
        : "r"(a[0]), "r"(a[1]), "r"(a[2]), "r"(a[3]), "r"(b[0]), "r"(b[1]));
}
__device__ __forceinline__ void ldmatrix_x4(uint32_t* r, uint32_t addr) {
    asm volatile("ldmatrix.sync.aligned.m8n8.x4.shared.b16 {%0,%1,%2,%3}, [%4];"
                 : "=r"(r[0]), "=r"(r[1]), "=r"(r[2]), "=r"(r[3]) : "r"(addr));
}
__device__ __forceinline__ void ldmatrix_x2(uint32_t* r, uint32_t addr) {
    asm volatile("ldmatrix.sync.aligned.m8n8.x2.shared.b16 {%0,%1}, [%2];"
                 : "=r"(r[0]), "=r"(r[1]) : "r"(addr));
}

// ---------------------------------------------------------------------------
// Kernel 1: L2-normalize + int8 quantize. One warp per row.
// q = round(v * 127 / max|v|);  scale = max|v| / (127*||v||)
// ---------------------------------------------------------------------------
__global__ __launch_bounds__(256) void normalize_kernel(const float* __restrict__ s1,
                                                        const float* __restrict__ s2) {
    int wid = threadIdx.x >> 5, lane = threadIdx.x & 31;
    int row = blockIdx.x * 8 + wid;          // 0 .. 32767
    const float* src;
    signed char* dst;
    float* scp;
    int srow;
    if (row < BATCH * L) {
        srow = row;
        src = s1 + (size_t)srow * D;
        dst = g_q1 + (size_t)srow * D;
        scp = g_sc1 + srow;
    } else {
        srow = row - BATCH * L;
        src = s2 + (size_t)srow * D;
        dst = g_q2 + (size_t)srow * D;
        scp = g_sc2 + srow;
    }
    const float4* s4 = (const float4*)src;
    float4 v[6];
    float ss = 0.f, mx = 0.f;
    #pragma unroll
    for (int i = 0; i < 6; i++) {
        v[i] = s4[lane + 32 * i];
        ss += v[i].x * v[i].x + v[i].y * v[i].y + v[i].z * v[i].z + v[i].w * v[i].w;
        mx = fmaxf(mx, fmaxf(fmaxf(fabsf(v[i].x), fabsf(v[i].y)),
                             fmaxf(fabsf(v[i].z), fabsf(v[i].w))));
    }
    #pragma unroll
    for (int o = 16; o > 0; o >>= 1) {
        ss += __shfl_xor_sync(0xffffffffu, ss, o);
        mx = fmaxf(mx, __shfl_xor_sync(0xffffffffu, mx, o));
    }
    float qmul = 127.0f / mx;
    if (lane == 0)
        *scp = mx * rsqrtf(ss) * (1.0f / 127.0f);
    #pragma unroll
    for (int i = 0; i < 6; i++) {
        char4 c;
        c.x = (signed char)__float2int_rn(v[i].x * qmul);
        c.y = (signed char)__float2int_rn(v[i].y * qmul);
        c.z = (signed char)__float2int_rn(v[i].z * qmul);
        c.w = (signed char)__float2int_rn(v[i].w * qmul);
        ((char4*)dst)[lane + 32 * i] = c;
    }
}

// ---------------------------------------------------------------------------
// Kernel 2: int8 GEMM, native mma.m16n8k32 + ldmatrix. CTA 128x128, BKI=64,
// 8 warps (2Mx4N, 64x32 warp tile), 3-stage cp.async, LDQ=80 (conflict-free).
// Epilogue: int acc -> smem -> dist = 1 - acc*s1[i]*s2[j] -> packed half
// uint4 stores into g_dskH skewed layout.
// ---------------------------------------------------------------------------
#define BM 128
#define BN 128
#define BKI 64
#define STAGES 3
#define NITERI (D / BKI)    // 12
#define LDQ 80              // int8 smem row stride (bytes)
#define LDC_S 132           // padded int32 epi row
#define STAGE_BYTES (2 * BM * LDQ)            // A+B per stage = 20480 B
#define SMEM_BYTES (128 * LDC_S * 4)          // 67584 B  (> 3*20480 = 61440)

__global__ __launch_bounds__(256) void gemm_dist_kernel() {
    extern __shared__ char smem[];
    signed char* sA[STAGES];
    signed char* sB[STAGES];
    #pragma unroll
    for (int s = 0; s < STAGES; s++) {
        sA[s] = (signed char*)(smem + s * STAGE_BYTES);
        sB[s] = sA[s] + BM * LDQ;
    }
    __shared__ float s1s[128], s2s[128];

    int tid = threadIdx.x;
    int lane = tid & 31;
    int b  = blockIdx.z;
    int m0 = blockIdx.y * BM;
    int n0 = blockIdx.x * BN;
    const signed char* A  = g_q1 + (size_t)b * L * D;
    const signed char* Bm = g_q2 + (size_t)b * L * D;

    int warp = tid >> 5;
    int wm = warp & 1;        // 2 warps in M (64 rows)
    int wn = warp >> 1;       // 4 warps in N (32 cols)

    // global->smem load indices: chunk id = tid + it*256, row = id>>2, col=(id&3)*16
    int lr = tid >> 2;        // 0..63
    int lc = (tid & 3) * 16;

    // ldmatrix per-lane address parts
    int a_row = (lane & 7) + ((lane >> 3) & 1) * 8;   // 0..15
    int a_kof = (lane >> 4) * 16;                     // 0 or 16
    int b_row = lane & 7;                             // n within 8-block
    int b_kof = ((lane >> 3) & 1) * 16;               // 0 or 16 (lanes 0-15 used)

    int acc[4][4][4];         // [mi][nb][reg]
    #pragma unroll
    for (int mi = 0; mi < 4; mi++)
        #pragma unroll
        for (int nb = 0; nb < 4; nb++)
            #pragma unroll
            for (int q = 0; q < 4; q++)
                acc[mi][nb][q] = 0;

    // prologue: stages 0, 1
    #pragma unroll
    for (int s = 0; s < 2; s++) {
        int k0 = s * BKI;
        #pragma unroll
        for (int it = 0; it < 2; it++) {
            cp16(smem_u32(&sA[s][(lr + it * 64) * LDQ + lc]),
                 A + (size_t)(m0 + lr + it * 64) * D + k0 + lc);
            cp16(smem_u32(&sB[s][(lr + it * 64) * LDQ + lc]),
                 Bm + (size_t)(n0 + lr + it * 64) * D + k0 + lc);
        }
        CP_COMMIT();
    }

    for (int c = 0; c < NITERI; c++) {
        CP_WAIT1();
        __syncthreads();
        int st = c % STAGES;
        uint32_t sAst = smem_u32(sA[st]);
        uint32_t sBst = smem_u32(sB[st]);

        #pragma unroll
        for (int kk = 0; kk < BKI; kk += 32) {
            uint32_t af[4][4];
            uint32_t bf[4][2];
            #pragma unroll
            for (int mi = 0; mi < 4; mi++)
                ldmatrix_x4(af[mi],
                    sAst + (wm * 64 + mi * 16 + a_row) * LDQ + kk + a_kof);
            #pragma unroll
            for (int nb = 0; nb < 4; nb++)
                ldmatrix_x2(bf[nb],
                    sBst + (wn * 32 + nb * 8 + b_row) * LDQ + kk + b_kof);
            #pragma unroll
            for (int mi = 0; mi < 4; mi++)
                #pragma unroll
                for (int nb = 0; nb < 4; nb++)
                    mma_s8_16832(acc[mi][nb], af[mi], bf[nb]);
        }

        if (c + 2 < NITERI) {
            int sn = (c + 2) % STAGES;
            int k0 = (c + 2) * BKI;
            #pragma unroll
            for (int it = 0; it < 2; it++) {
                cp16(smem_u32(&sA[sn][(lr + it * 64) * LDQ + lc]),
                     A + (size_t)(m0 + lr + it * 64) * D + k0 + lc);
                cp16(smem_u32(&sB[sn][(lr + it * 64) * LDQ + lc]),
                     Bm + (size_t)(n0 + lr + it * 64) * D + k0 + lc);
            }
        }
        CP_COMMIT();
    }

    // epilogue: int acc -> smem, rescale, packed half uint4 stores
    CP_WAIT0();
    __syncthreads();
    if (tid < 128) {
        s1s[tid] = g_sc1[b * L + m0 + tid];
        s2s[tid] = g_sc2[b * L + n0 + tid];
    }
    int* CsI = (int*)smem;
    // mma m16n8 acc layout: lane holds rows (l>>2), (l>>2)+8; cols 2*(l&3), +1
    int crow = lane >> 2;
    int ccol = 2 * (lane & 3);
    #pragma unroll
    for (int mi = 0; mi < 4; mi++)
        #pragma unroll
        for (int nb = 0; nb < 4; nb++) {
            int r0 = wm * 64 + mi * 16 + crow;
            int cc = wn * 32 + nb * 8 + ccol;
            *(int2*)&CsI[r0 * LDC_S + cc]       = make_int2(acc[mi][nb][0], acc[mi][nb][1]);
            *(int2*)&CsI[(r0 + 8) * LDC_S + cc] = make_int2(acc[mi][nb][2], acc[mi][nb][3]);
        }
    __syncthreads();

    __half* dbase = g_dskH + (size_t)b * G2 * 2048;
    int jgl = tid & 31;           // local j group (4 cols), col = n0 + 4*jgl
    int sub = tid >> 5;           // 0..7

    float sb0 = s2s[4 * jgl], sb1 = s2s[4 * jgl + 1];
    float sb2 = s2s[4 * jgl + 2], sb3 = s2s[4 * jgl + 3];

    #pragma unroll
    for (int it = 0; it < 8; it++) {
        int il2 = sub + it * 8;                      // local row pair 0..63
        int4 r0 = *(int4*)&CsI[(2 * il2)     * LDC_S + 4 * jgl];
        int4 r1 = *(int4*)&CsI[(2 * il2 + 1) * LDC_S + 4 * jgl];
        float sa0 = s1s[2 * il2], sa1 = s1s[2 * il2 + 1];
        uint4 o;
        __half2* ph = (__half2*)&o;
        ph[0] = __floats2half2_rn(1.0f - (float)r0.x * sa0 * sb0,
                                  1.0f - (float)r0.y * sa0 * sb1);
        ph[1] = __floats2half2_rn(1.0f - (float)r0.z * sa0 * sb2,
                                  1.0f - (float)r0.w * sa0 * sb3);
        ph[2] = __floats2half2_rn(1.0f - (float)r1.x * sa1 * sb0,
                                  1.0f - (float)r1.y * sa1 * sb1);
        ph[3] = __floats2half2_rn(1.0f - (float)r1.z * sa1 * sb2,
                                  1.0f - (float)r1.w * sa1 * sb3);
        int g = (m0 >> 1) + il2 + (n0 >> 2) + jgl;
        *(uint4*)(dbase + (size_t)g * 2048 + ((n0 >> 2) + jgl) * 8) = o;
    }
}

// ---------------------------------------------------------------------------
// Kernel 3: DTW wavefront (round-4 proven version). 256 threads, thread jg
// owns cols [4jg,4jg+4), 2 rows per macro-step, 768 steps. One uint4 (8 half)
// dist load per thread per step, min-plus prefix form. Neighbor handoff via
// shfl + parity double-buffered smem; one __syncthreads per step.
// ---------------------------------------------------------------------------
#define PF 8

__global__ __launch_bounds__(256) void dtw_kernel(float* __restrict__ out) {
    int b = blockIdx.x;
    int jg = threadIdx.x, lane = jg & 31, w = jg >> 5;

    const uint4* base = (const uint4*)(g_dskH + (size_t)b * G2 * 2048) + jg;
    // g row stride = 2048 halfs = 256 uint4

    __shared__ float pub[2][8][2];
    if (lane < 2) { pub[0][w][lane] = BIG; pub[1][w][lane] = BIG; }
    __syncthreads();

    float p0 = BIG, p1 = BIG, p2 = BIG, p3 = BIG;   // prev row of own 4 cols
    float c3r0 = BIG, c3r1 = BIG, prev_vb = BIG;
    float res = 0.0f;

    uint4 ring[PF];
    #pragma unroll
    for (int s = 0; s < PF; s++)
        ring[s] = base[(size_t)min(s, G2 - 1) * 256];

    #pragma unroll 8
    for (int S = 0; S < 768; S++) {
        uint4 u = ring[S & (PF - 1)];
        ring[S & (PF - 1)] = base[(size_t)min(S + PF, G2 - 1) * 256];

        float va = __shfl_up_sync(0xffffffffu, c3r0, 1);  // dtw[i0][4jg-1]
        float vb = __shfl_up_sync(0xffffffffu, c3r1, 1);  // dtw[i0+1][4jg-1]
        if (lane == 0) {
            if (w > 0) {
                va = pub[(S & 1) ^ 1][w - 1][0];
                vb = pub[(S & 1) ^ 1][w - 1][1];
            } else { va = BIG; vb = BIG; }
        }

        int i0 = 2 * (S - jg);
        if ((unsigned)i0 < 1024u) {
            float2 q0 = __half22float2(((const __half2*)&u)[0]);
            float2 q1 = __half22float2(((const __half2*)&u)[1]);
            float2 q2 = __half22float2(((const __half2*)&u)[2]);
            float2 q3 = __half22float2(((const __half2*)&u)[3]);
            // row i0 (min-plus prefix form)
            float D0 = q0.x, D1 = D0 + q0.y, D2 = D1 + q1.x, D3 = D2 + q1.y;
            float f0 = fminf(prev_vb, p0);
            float f1 = fminf(p0, p1) - D0;
            float f2 = fminf(p1, p2) - D1;
            float f3 = fminf(p2, p3) - D2;
            float m0 = fminf(va, f0);
            if (i0 == 0 && jg == 0) m0 = 0.0f;
            float m1 = fminf(m0, f1);
            float m2 = fminf(m1, f2);
            float m3 = fminf(m2, f3);
            float c0 = D0 + m0, c1 = D1 + m1, c2 = D2 + m2, c3 = D3 + m3;
            // row i0+1
            float E0 = q2.x, E1 = E0 + q2.y, E2 = E1 + q3.x, E3 = E2 + q3.y;
            float h0 = fminf(va, c0);
            float h1 = fminf(c0, c1) - E0;
            float h2 = fminf(c1, c2) - E1;
            float h3 = fminf(c2, c3) - E2;
            float n0 = fminf(vb, h0);
            float n1 = fminf(n0, h1);
            float n2 = fminf(n1, h2);
            float n3 = fminf(n2, h3);
            p0 = E0 + n0; p1 = E1 + n1; p2 = E2 + n2; p3 = E3 + n3;
            c3r0 = c3; c3r1 = p3;
            if (i0 == 1022 && jg == 255) res = p3;
        }
        prev_vb = vb;
        if (lane == 31) { pub[S & 1][w][0] = c3r0; pub[S & 1][w][1] = c3r1; }
        __syncthreads();
    }

    if (jg == 255)
        out[b] = 1.0f / (1.0f + res * (1.0f / 2048.0f));
}

// ---------------------------------------------------------------------------
extern "C" void kernel_launch(void* const* d_in, const int* in_sizes, int n_in,
                              void* d_out, int out_size) {
    const float* s1 = (const float*)d_in[0];
    const float* s2 = (const float*)d_in[1];
    float* out = (float*)d_out;

    cudaFuncSetAttribute(gemm_dist_kernel,
                         cudaFuncAttributeMaxDynamicSharedMemorySize, SMEM_BYTES);

    normalize_kernel<<<4096, 256>>>(s1, s2);
    gemm_dist_kernel<<<dim3(L / BN, L / BM, BATCH), 256, SMEM_BYTES>>>();
    dtw_kernel<<<BATCH, 256>>>(out);
}